// round 8
// baseline (speedup 1.0000x reference)
#include <cuda_runtime.h>
#include <cstdint>

#define NEG_BIG 1e12f
#define NB 32
#define NS 4096
#define ND 128
#define NH 4
#define NROWS (NB * NS)       // 131072
#define GRID1 148
#define NSLOTS (NB * 128)     // 128 32-row unit slots per batch

// scratch
__device__ float g_w_scratch[NB * NS * NH];   // 2 MB fallback
__device__ float g_part[8 * NB * NH * ND];    // 512 KB partials
__device__ int   g_idx[NB * NS];              // compacted row indices per batch
__device__ int   g_cnt[NB];                   // unmasked count per batch
__device__ int   g_ticket;                    // dynamic work ticket
__device__ int   g_done[NB];                  // k3 per-batch completion count
__device__ float g_stats[NB * 8];             // per-batch {max[4], invZ[4]}

// ---------------------------------------------------------------------------
// SMEM layout for k1 (bytes)
// ---------------------------------------------------------------------------
#define OFF_B    0                 // B fragments: 4096 slots x 16B = 65536
#define OFF_WO   65536             // 2048
#define OFF_PED  67584             // 4 pairs x 2 bufs x 64 float4 = 8192
#define OFF_TK   75776             // 4 ints (+pad to 64)
#define OFF_A    75840             // 8 x (32 rows x APITCH)
#define APITCH   528
#define ASZ      (32 * APITCH)     // 16896 per (pair,buf)
#define SMEM_K1  (OFF_A + 8 * ASZ) // 211008

// ---------------------------------------------------------------------------
// helpers
// ---------------------------------------------------------------------------
__device__ __forceinline__ void split2(float v0, float v1,
                                       uint32_t& hi, uint32_t& lo) {
    uint32_t u0 = __float_as_uint(v0), u1 = __float_as_uint(v1);
    uint32_t h;
    asm("prmt.b32 %0, %1, %2, 0x7632;" : "=r"(h) : "r"(u0), "r"(u1));
    float r0 = v0 - __uint_as_float(u0 & 0xFFFF0000u);
    float r1 = v1 - __uint_as_float(u1 & 0xFFFF0000u);
    uint32_t l;
    asm("cvt.rn.bf16x2.f32 %0, %1, %2;" : "=r"(l) : "f"(r1), "f"(r0));
    hi = h; lo = l;
}

__device__ __forceinline__ void mma16816(float* c,
    uint32_t a0, uint32_t a1, uint32_t a2, uint32_t a3,
    uint32_t b0, uint32_t b1)
{
    asm volatile(
        "mma.sync.aligned.m16n8k16.row.col.f32.bf16.bf16.f32 "
        "{%0,%1,%2,%3}, {%4,%5,%6,%7}, {%8,%9}, {%0,%1,%2,%3};"
        : "+f"(c[0]), "+f"(c[1]), "+f"(c[2]), "+f"(c[3])
        : "r"(a0), "r"(a1), "r"(a2), "r"(a3), "r"(b0), "r"(b1));
}

__device__ __forceinline__ float fast_tanh(float a) {
    float r;
    asm("tanh.approx.f32 %0, %1;" : "=f"(r) : "f"(a));
    return r;
}

#define PAIR_BAR(id) asm volatile("bar.sync %0, 64;" :: "r"(id) : "memory")

__device__ __forceinline__ int grab_slot() {
    for (;;) {
        int s = atomicAdd(&g_ticket, 1);
        if (s >= NSLOTS) return -1;
        int b = s >> 7, u = s & 127;
        if (u * 32 < g_cnt[b]) return s;
    }
}

// ---------------------------------------------------------------------------
// K0: per-batch order-preserving compaction of unmasked row indices +
// exact-zero fill of w for masked rows (matches fp32 softmax underflow).
// ---------------------------------------------------------------------------
__global__ __launch_bounds__(256) void k0_compact(
    const int* __restrict__ mask, float* __restrict__ w)
{
    __shared__ int wsum[8];
    const int b = blockIdx.x, tid = threadIdx.x;
    if (tid == 0) {
        if (b == 0) g_ticket = 0;
        g_done[b] = 0;
    }
    const int base = tid * 16;
    const int* mb = mask + b * NS;
    int m[16], c = 0;
#pragma unroll
    for (int i = 0; i < 16; i++) { m[i] = mb[base + i]; c += m[i]; }
    const int lane = tid & 31, wd = tid >> 5;
    int sc = c;
#pragma unroll
    for (int off = 1; off < 32; off <<= 1) {
        int n = __shfl_up_sync(0xffffffffu, sc, off);
        if (lane >= off) sc += n;
    }
    if (lane == 31) wsum[wd] = sc;
    __syncthreads();
    int woff = 0;
#pragma unroll
    for (int i = 0; i < 8; i++) woff += (i < wd) ? wsum[i] : 0;
    int ww = woff + sc - c;   // exclusive prefix
    float4* wb4 = ((float4*)w) + b * NS;
    const float4 zero = make_float4(0.f, 0.f, 0.f, 0.f);
#pragma unroll
    for (int i = 0; i < 16; i++) {
        if (m[i]) g_idx[b * NS + (ww++)] = base + i;
        else wb4[base + i] = zero;
    }
    if (tid == 255) g_cnt[b] = ww;
}

// ---------------------------------------------------------------------------
// K1: persistent bf16-split mma.sync (x@Wk) -> tanh -> @Wo on COMPACTED rows.
// ---------------------------------------------------------------------------
__global__ __launch_bounds__(256, 1) void k1_mma_kernel(
    const float* __restrict__ x,
    const float* __restrict__ Wk, const float* __restrict__ Wo,
    float* __restrict__ logits)
{
    extern __shared__ char smem[];
    const int tid  = threadIdx.x;
    const int wid  = tid >> 5;
    const int lane = tid & 31;
    const int g    = lane >> 2;
    const int t    = lane & 3;
    const int p    = wid >> 1;      // pair 0..3
    const int nw   = wid & 1;
    const int qp   = tid & 63;

    int* tk = (int*)(smem + OFF_TK);
    float4* wo4s = (float4*)(smem + OFF_WO);
    if (tid < 128) wo4s[tid] = ((const float4*)Wo)[tid];

    // B fragments (Wk split hi/lo, mma-fragment order)
    for (int s = tid; s < 4096; s += 256) {
        int sl = s & 31, sg = sl >> 2, st = sl & 3;
        int idx = s >> 5, ks = idx >> 4, nt = idx & 15;
        int n = nt * 8 + sg;
        int k0 = ks * 16 + st * 2;
        float v00 = Wk[k0 * 128 + n];
        float v01 = Wk[k0 * 128 + 128 + n];
        float v10 = Wk[(k0 + 8) * 128 + n];
        float v11 = Wk[(k0 + 9) * 128 + n];
        uint32_t b0h, b0l, b1h, b1l;
        split2(v00, v01, b0h, b0l);
        split2(v10, v11, b1h, b1l);
        uint4 u; u.x = b0h; u.y = b1h; u.z = b0l; u.w = b1l;
        *(uint4*)(smem + OFF_B + s * 16) = u;
    }
    __syncthreads();

    const float4* xg4 = (const float4*)x;
    float4* pedbase = (float4*)(smem + OFF_PED);

    if (nw == 0 && lane == 0) tk[p] = grab_slot();
    PAIR_BAR(1 + p);
    int slot = tk[p];

    if (slot >= 0) {
        int b = slot >> 7, u = slot & 127, cnt = g_cnt[b];
        const int* ib = g_idx + b * NS;
        char* dst = smem + OFF_A + (p * 2) * ASZ;
#pragma unroll
        for (int i = 0; i < 16; i++) {
            int idx = qp + 64 * i;
            int row = idx >> 5, c4 = idx & 31;
            int j = u * 32 + row; if (j > cnt - 1) j = cnt - 1;
            int s = ib[j];
            float4 v = xg4[((size_t)b * NS + s) * 32 + c4];
            uint32_t h0, l0, h1, l1;
            split2(v.x, v.y, h0, l0);
            split2(v.z, v.w, h1, l1);
            uint4 uu; uu.x = h0; uu.y = l0; uu.z = h1; uu.w = l1;
            *(uint4*)(dst + row * APITCH + c4 * 16) = uu;
        }
        if (nw == 0 && lane == 0) tk[p] = grab_slot();
    }
    PAIR_BAR(1 + p);
    int nslot = (slot >= 0) ? tk[p] : -1;

    int buf = 0;
    while (slot >= 0) {
        const int b = slot >> 7, u = slot & 127;

        float4 xr[16];
        if (nslot >= 0) {
            int bn = nslot >> 7, un = nslot & 127, cntn = g_cnt[bn];
            const int* ibn = g_idx + bn * NS;
#pragma unroll
            for (int i = 0; i < 16; i++) {
                int idx = qp + 64 * i;
                int row = idx >> 5, c4 = idx & 31;
                int j = un * 32 + row; if (j > cntn - 1) j = cntn - 1;
                int s = ibn[j];
                xr[i] = xg4[((size_t)bn * NS + s) * 32 + c4];
            }
        }

        const char* Abuf = smem + OFF_A + (p * 2 + buf) * ASZ;
        float acc[2][8][4];
#pragma unroll
        for (int mt = 0; mt < 2; mt++)
#pragma unroll
            for (int nt = 0; nt < 8; nt++)
#pragma unroll
                for (int c = 0; c < 4; c++) acc[mt][nt][c] = 0.0f;

#pragma unroll
        for (int ks = 0; ks < 8; ks++) {
            uint4 B[8];
#pragma unroll
            for (int nt = 0; nt < 8; nt++)
                B[nt] = *(const uint4*)(smem + OFF_B +
                        (((ks * 16) + (nw * 8 + nt)) * 32 + lane) * 16);
#pragma unroll
            for (int mt = 0; mt < 2; mt++) {
                const char* Ar = Abuf + mt * 16 * APITCH;
                int pk = ks * 8 + t;
                uint2 ax0 = *(const uint2*)(Ar + g * APITCH + pk * 8);
                uint2 ax1 = *(const uint2*)(Ar + (g + 8) * APITCH + pk * 8);
                uint2 ax2 = *(const uint2*)(Ar + g * APITCH + (pk + 4) * 8);
                uint2 ax3 = *(const uint2*)(Ar + (g + 8) * APITCH + (pk + 4) * 8);
#pragma unroll
                for (int nt = 0; nt < 8; nt++)
                    mma16816(acc[mt][nt], ax0.x, ax1.x, ax2.x, ax3.x,
                             B[nt].x, B[nt].y);
#pragma unroll
                for (int nt = 0; nt < 8; nt++)
                    mma16816(acc[mt][nt], ax0.y, ax1.y, ax2.y, ax3.y,
                             B[nt].x, B[nt].y);
#pragma unroll
                for (int nt = 0; nt < 8; nt++)
                    mma16816(acc[mt][nt], ax0.x, ax1.x, ax2.x, ax3.x,
                             B[nt].z, B[nt].w);
            }
        }

        float hp[4][4];
#pragma unroll
        for (int r = 0; r < 4; r++)
#pragma unroll
            for (int h = 0; h < 4; h++) hp[r][h] = 0.0f;

#pragma unroll
        for (int nt = 0; nt < 8; nt++) {
            int col = nw * 64 + nt * 8 + 2 * t;
            float4 w0 = wo4s[col];
            float4 w1 = wo4s[col + 1];
#pragma unroll
            for (int mt = 0; mt < 2; mt++) {
                float* c = acc[mt][nt];
                float t0 = fast_tanh(c[0]);
                float t1 = fast_tanh(c[1]);
                float t2 = fast_tanh(c[2]);
                float t3 = fast_tanh(c[3]);
                int r0 = mt * 2, r1 = mt * 2 + 1;
                hp[r0][0] = fmaf(t0, w0.x, fmaf(t1, w1.x, hp[r0][0]));
                hp[r0][1] = fmaf(t0, w0.y, fmaf(t1, w1.y, hp[r0][1]));
                hp[r0][2] = fmaf(t0, w0.z, fmaf(t1, w1.z, hp[r0][2]));
                hp[r0][3] = fmaf(t0, w0.w, fmaf(t1, w1.w, hp[r0][3]));
                hp[r1][0] = fmaf(t2, w0.x, fmaf(t3, w1.x, hp[r1][0]));
                hp[r1][1] = fmaf(t2, w0.y, fmaf(t3, w1.y, hp[r1][1]));
                hp[r1][2] = fmaf(t2, w0.z, fmaf(t3, w1.z, hp[r1][2]));
                hp[r1][3] = fmaf(t2, w0.w, fmaf(t3, w1.w, hp[r1][3]));
            }
        }
#pragma unroll
        for (int off = 1; off <= 2; off <<= 1)
#pragma unroll
            for (int r = 0; r < 4; r++)
#pragma unroll
                for (int h = 0; h < 4; h++)
                    hp[r][h] += __shfl_xor_sync(0xffffffffu, hp[r][h], off);

        float4* pedp = pedbase + (p * 2 + buf) * 64;
        if (t == 0) {
            pedp[nw * 32 + g]      = make_float4(hp[0][0], hp[0][1], hp[0][2], hp[0][3]);
            pedp[nw * 32 + 8 + g]  = make_float4(hp[1][0], hp[1][1], hp[1][2], hp[1][3]);
            pedp[nw * 32 + 16 + g] = make_float4(hp[2][0], hp[2][1], hp[2][2], hp[2][3]);
            pedp[nw * 32 + 24 + g] = make_float4(hp[3][0], hp[3][1], hp[3][2], hp[3][3]);
        }

        if (nslot >= 0) {
            char* dst = smem + OFF_A + (p * 2 + (1 - buf)) * ASZ;
#pragma unroll
            for (int i = 0; i < 16; i++) {
                int idx = qp + 64 * i;
                int row = idx >> 5, c4 = idx & 31;
                uint32_t h0, l0, h1, l1;
                split2(xr[i].x, xr[i].y, h0, l0);
                split2(xr[i].z, xr[i].w, h1, l1);
                uint4 uu; uu.x = h0; uu.y = l0; uu.z = h1; uu.w = l1;
                *(uint4*)(dst + row * APITCH + c4 * 16) = uu;
            }
            if (nw == 0 && lane == 0) tk[p] = grab_slot();
        }

        PAIR_BAR(1 + p);

        if (nw == 0) {
            int cnt = g_cnt[b];
            int j = u * 32 + lane;
            if (j < cnt) {
                float4 a = pedp[lane];
                float4 bb = pedp[32 + lane];
                int s = g_idx[b * NS + j];
                float4 o;
                o.x = a.x + bb.x; o.y = a.y + bb.y;
                o.z = a.z + bb.z; o.w = a.w + bb.w;
                ((float4*)logits)[b * NS + s] = o;
            }
        }

        slot = nslot;
        nslot = (slot >= 0) ? tk[p] : -1;
        buf ^= 1;
    }
}

// ---------------------------------------------------------------------------
// K2: stats pass — per (b,h) masked max and 1/sum(exp). No w write.
// ---------------------------------------------------------------------------
__global__ __launch_bounds__(512) void k2_stats(
    const float* __restrict__ logits, const int* __restrict__ mask)
{
    __shared__ float red[16][4];
    __shared__ float bc[8];
    const int b = blockIdx.x, tid = threadIdx.x;
    const int lane = tid & 31, wd = tid >> 5;

    const float4* p = ((const float4*)logits) + b * NS;
    const int* mb = mask + b * NS;

    float4 v[8]; int mk[8];
#pragma unroll
    for (int i = 0; i < 8; i++) {
        int r = tid + 512 * i;
        mk[i] = mb[r];
        v[i] = p[r];
    }

    const float NINF = -3.4e38f;
    float m0 = NINF, m1 = NINF, m2 = NINF, m3 = NINF;
#pragma unroll
    for (int i = 0; i < 8; i++) {
        if (mk[i]) {
            m0 = fmaxf(m0, v[i].x); m1 = fmaxf(m1, v[i].y);
            m2 = fmaxf(m2, v[i].z); m3 = fmaxf(m3, v[i].w);
        }
    }
#pragma unroll
    for (int off = 16; off >= 1; off >>= 1) {
        m0 = fmaxf(m0, __shfl_xor_sync(0xffffffffu, m0, off));
        m1 = fmaxf(m1, __shfl_xor_sync(0xffffffffu, m1, off));
        m2 = fmaxf(m2, __shfl_xor_sync(0xffffffffu, m2, off));
        m3 = fmaxf(m3, __shfl_xor_sync(0xffffffffu, m3, off));
    }
    if (lane == 0) { red[wd][0] = m0; red[wd][1] = m1; red[wd][2] = m2; red[wd][3] = m3; }
    __syncthreads();
    if (tid < 4) {
        float m = red[0][tid];
#pragma unroll
        for (int i = 1; i < 16; i++) m = fmaxf(m, red[i][tid]);
        bc[tid] = m;
    }
    __syncthreads();
    m0 = bc[0]; m1 = bc[1]; m2 = bc[2]; m3 = bc[3];

    float s0 = 0.f, s1 = 0.f, s2 = 0.f, s3 = 0.f;
#pragma unroll
    for (int i = 0; i < 8; i++) {
        if (mk[i]) {
            s0 += __expf(v[i].x - m0);
            s1 += __expf(v[i].y - m1);
            s2 += __expf(v[i].z - m2);
            s3 += __expf(v[i].w - m3);
        }
    }
#pragma unroll
    for (int off = 16; off >= 1; off >>= 1) {
        s0 += __shfl_xor_sync(0xffffffffu, s0, off);
        s1 += __shfl_xor_sync(0xffffffffu, s1, off);
        s2 += __shfl_xor_sync(0xffffffffu, s2, off);
        s3 += __shfl_xor_sync(0xffffffffu, s3, off);
    }
    if (lane == 0) { red[wd][0] = s0; red[wd][1] = s1; red[wd][2] = s2; red[wd][3] = s3; }
    __syncthreads();
    if (tid < 4) {
        float s = 0.f;
#pragma unroll
        for (int i = 0; i < 16; i++) s += red[i][tid];
        bc[4 + tid] = 1.0f / s;
    }
    __syncthreads();
    if (tid < 8) g_stats[b * 8 + tid] = bc[tid];
}

// ---------------------------------------------------------------------------
// K3: fused softmax-apply + pooling over COMPACTED rows with software-
// pipelined index prefetch, + per-batch final reduction (threadfence pattern;
// fixed q-order sum -> deterministic). Writes w in place and pooled.
// ---------------------------------------------------------------------------
#define K3_ACC(wv, xv)                                                         \
    do {                                                                       \
        a[0][0] = fmaf(wv.x, xv.x, a[0][0]); a[0][1] = fmaf(wv.x, xv.y, a[0][1]); \
        a[0][2] = fmaf(wv.x, xv.z, a[0][2]); a[0][3] = fmaf(wv.x, xv.w, a[0][3]); \
        a[1][0] = fmaf(wv.y, xv.x, a[1][0]); a[1][1] = fmaf(wv.y, xv.y, a[1][1]); \
        a[1][2] = fmaf(wv.y, xv.z, a[1][2]); a[1][3] = fmaf(wv.y, xv.w, a[1][3]); \
        a[2][0] = fmaf(wv.z, xv.x, a[2][0]); a[2][1] = fmaf(wv.z, xv.y, a[2][1]); \
        a[2][2] = fmaf(wv.z, xv.z, a[2][2]); a[2][3] = fmaf(wv.z, xv.w, a[2][3]); \
        a[3][0] = fmaf(wv.w, xv.x, a[3][0]); a[3][1] = fmaf(wv.w, xv.y, a[3][1]); \
        a[3][2] = fmaf(wv.w, xv.z, a[3][2]); a[3][3] = fmaf(wv.w, xv.w, a[3][3]); \
    } while (0)

#define K3_SOFT(wv, lv)                                        \
    do {                                                       \
        wv.x = __expf(lv.x - m4.x) * z4.x;                     \
        wv.y = __expf(lv.y - m4.y) * z4.y;                     \
        wv.z = __expf(lv.z - m4.z) * z4.z;                     \
        wv.w = __expf(lv.w - m4.w) * z4.w;                     \
    } while (0)

__global__ __launch_bounds__(512, 2) void k3_kernel(
    const float* __restrict__ x, float* __restrict__ w,
    float* __restrict__ part, float* __restrict__ pooled)
{
    __shared__ float sm[16][512];
    __shared__ int isLast;
    const int q = blockIdx.x;    // 0..7
    const int b = blockIdx.y;
    const int tid = threadIdx.x;
    const int d4 = tid & 31;
    const int sg = tid >> 5;

    const int cnt = g_cnt[b];
    const int* ib = g_idx + b * NS;
    float4* wb4 = ((float4*)w) + b * NS;
    const float4* xp = ((const float4*)x) + (size_t)b * NS * 32;

    const float4 m4 = *(const float4*)&g_stats[b * 8];
    const float4 z4 = *(const float4*)&g_stats[b * 8 + 4];

    float a[4][4];
#pragma unroll
    for (int h = 0; h < 4; h++)
#pragma unroll
        for (int jj = 0; jj < 4; jj++) a[h][jj] = 0.0f;

    int j = q * 16 + sg;   // warp's first compacted index; stride 128

    // prefetch first index group
    int sc[4];
#pragma unroll
    for (int k = 0; k < 4; k++)
        sc[k] = (j + k * 128 < cnt) ? ib[j + k * 128] : -1;

    while (j < cnt) {
        // prefetch NEXT group's indices before consuming this group's data
        int sn[4];
        int jn = j + 512;
#pragma unroll
        for (int k = 0; k < 4; k++)
            sn[k] = (jn + k * 128 < cnt) ? ib[jn + k * 128] : -1;

        // data loads for the current group (up to 8 in flight)
        float4 l0, l1, l2, l3, x0, x1, x2, x3;
        if (sc[0] >= 0) { l0 = wb4[sc[0]]; x0 = xp[(size_t)sc[0] * 32 + d4]; }
        if (sc[1] >= 0) { l1 = wb4[sc[1]]; x1 = xp[(size_t)sc[1] * 32 + d4]; }
        if (sc[2] >= 0) { l2 = wb4[sc[2]]; x2 = xp[(size_t)sc[2] * 32 + d4]; }
        if (sc[3] >= 0) { l3 = wb4[sc[3]]; x3 = xp[(size_t)sc[3] * 32 + d4]; }

        if (sc[0] >= 0) {
            float4 w0; K3_SOFT(w0, l0);
            if (d4 == 0) wb4[sc[0]] = w0;
            K3_ACC(w0, x0);
        }
        if (sc[1] >= 0) {
            float4 w1; K3_SOFT(w1, l1);
            if (d4 == 0) wb4[sc[1]] = w1;
            K3_ACC(w1, x1);
        }
        if (sc[2] >= 0) {
            float4 w2; K3_SOFT(w2, l2);
            if (d4 == 0) wb4[sc[2]] = w2;
            K3_ACC(w2, x2);
        }
        if (sc[3] >= 0) {
            float4 w3; K3_SOFT(w3, l3);
            if (d4 == 0) wb4[sc[3]] = w3;
            K3_ACC(w3, x3);
        }

        sc[0] = sn[0]; sc[1] = sn[1]; sc[2] = sn[2]; sc[3] = sn[3];
        j = jn;
    }

#pragma unroll
    for (int h = 0; h < 4; h++)
#pragma unroll
        for (int jj = 0; jj < 4; jj++)
            sm[sg][h * 128 + d4 * 4 + jj] = a[h][jj];
    __syncthreads();

    float ssum = 0.0f;
#pragma unroll
    for (int gi = 0; gi < 16; gi++) ssum += sm[gi][tid];
    part[(q * NB + b) * 512 + tid] = ssum;

    // per-batch final combine: last of the 8 blocks for batch b sums q=0..7
    __threadfence();
    if (tid == 0) {
        int old = atomicAdd(&g_done[b], 1);
        isLast = (old == 7);
    }
    __syncthreads();
    if (isLast) {
        float s = 0.0f;
#pragma unroll
        for (int k = 0; k < 8; k++)
            s += __ldcg(&part[(k * NB + b) * 512 + tid]);
        pooled[b * 512 + tid] = s;
    }
}

// ---------------------------------------------------------------------------
extern "C" void kernel_launch(void* const* d_in, const int* in_sizes, int n_in,
                              void* d_out, int out_size)
{
    const float* x   = (const float*)d_in[0];
    const int*   msk = (const int*)d_in[1];
    const float* Wk  = (const float*)d_in[2];
    const float* Wo  = (const float*)d_in[3];
    float* out = (float*)d_out;

    const int pooled_elems = NB * NH * ND;   // 16384
    const int w_elems = NB * NS * NH;        // 524288

    float* pooled = out;
    float* wbuf;
    if (out_size >= pooled_elems + w_elems) {
        wbuf = out + pooled_elems;
    } else {
        void* p = nullptr;
        cudaGetSymbolAddress(&p, g_w_scratch);
        wbuf = (float*)p;
    }

    cudaFuncSetAttribute(k1_mma_kernel,
                         cudaFuncAttributeMaxDynamicSharedMemorySize, SMEM_K1);

    k0_compact<<<NB, 256>>>(msk, wbuf);
    k1_mma_kernel<<<GRID1, 256, SMEM_K1>>>(x, Wk, Wo, wbuf);
    k2_stats<<<NB, 512>>>(wbuf, msk);

    void* pp = nullptr;
    cudaGetSymbolAddress(&pp, g_part);
    k3_kernel<<<dim3(8, NB), 512>>>(x, wbuf, (float*)pp, pooled);
}

// round 9
// speedup vs baseline: 1.1179x; 1.1179x over previous
#include <cuda_runtime.h>
#include <cstdint>

#define NEG_BIG 1e12f
#define NB 32
#define NS 4096
#define ND 128
#define NH 4
#define NROWS (NB * NS)       // 131072
#define GRID1 148
#define NSLOTS (NB * 128)     // 128 32-row unit slots per batch

// scratch
__device__ float g_w_scratch[NB * NS * NH];   // 2 MB fallback
__device__ float g_part[16 * NB * NH * ND];   // 1 MB partials
__device__ int   g_idx[NB * NS];              // compacted row indices per batch
__device__ int   g_cnt[NB];                   // unmasked count per batch
__device__ int   g_ticket;                    // dynamic work ticket
__device__ int   g_done[NB];                  // k3 per-batch completion count

// ---------------------------------------------------------------------------
// SMEM layout for k1 (bytes)
// ---------------------------------------------------------------------------
#define OFF_B    0                 // B fragments: 4096 slots x 16B = 65536
#define OFF_WO   65536             // 2048
#define OFF_PED  67584             // 4 pairs x 2 bufs x 64 float4 = 8192
#define OFF_TK   75776             // 4 ints (+pad to 64)
#define OFF_A    75840             // 8 x (32 rows x APITCH)
#define APITCH   528
#define ASZ      (32 * APITCH)     // 16896 per (pair,buf)
#define SMEM_K1  (OFF_A + 8 * ASZ) // 211008

// ---------------------------------------------------------------------------
// helpers
// ---------------------------------------------------------------------------
__device__ __forceinline__ void split2(float v0, float v1,
                                       uint32_t& hi, uint32_t& lo) {
    uint32_t u0 = __float_as_uint(v0), u1 = __float_as_uint(v1);
    uint32_t h;
    asm("prmt.b32 %0, %1, %2, 0x7632;" : "=r"(h) : "r"(u0), "r"(u1));
    float r0 = v0 - __uint_as_float(u0 & 0xFFFF0000u);
    float r1 = v1 - __uint_as_float(u1 & 0xFFFF0000u);
    uint32_t l;
    asm("cvt.rn.bf16x2.f32 %0, %1, %2;" : "=r"(l) : "f"(r1), "f"(r0));
    hi = h; lo = l;
}

__device__ __forceinline__ void mma16816(float* c,
    uint32_t a0, uint32_t a1, uint32_t a2, uint32_t a3,
    uint32_t b0, uint32_t b1)
{
    asm volatile(
        "mma.sync.aligned.m16n8k16.row.col.f32.bf16.bf16.f32 "
        "{%0,%1,%2,%3}, {%4,%5,%6,%7}, {%8,%9}, {%0,%1,%2,%3};"
        : "+f"(c[0]), "+f"(c[1]), "+f"(c[2]), "+f"(c[3])
        : "r"(a0), "r"(a1), "r"(a2), "r"(a3), "r"(b0), "r"(b1));
}

__device__ __forceinline__ float fast_tanh(float a) {
    float r;
    asm("tanh.approx.f32 %0, %1;" : "=f"(r) : "f"(a));
    return r;
}

#define PAIR_BAR(id) asm volatile("bar.sync %0, 64;" :: "r"(id) : "memory")

__device__ __forceinline__ int grab_slot() {
    for (;;) {
        int s = atomicAdd(&g_ticket, 1);
        if (s >= NSLOTS) return -1;
        int b = s >> 7, u = s & 127;
        if (u * 32 < g_cnt[b]) return s;
    }
}

// ---------------------------------------------------------------------------
// K0: per-batch order-preserving compaction of unmasked row indices +
// fill masked logits with -1e12 (so k2's softmax zeroes them exactly).
// ---------------------------------------------------------------------------
__global__ __launch_bounds__(256) void k0_compact(
    const int* __restrict__ mask, float* __restrict__ logits)
{
    __shared__ int wsum[8];
    const int b = blockIdx.x, tid = threadIdx.x;
    if (tid == 0) {
        if (b == 0) g_ticket = 0;
        g_done[b] = 0;
    }
    const int base = tid * 16;
    const int* mb = mask + b * NS;
    int m[16], c = 0;
#pragma unroll
    for (int i = 0; i < 16; i++) { m[i] = mb[base + i]; c += m[i]; }
    const int lane = tid & 31, wd = tid >> 5;
    int sc = c;
#pragma unroll
    for (int off = 1; off < 32; off <<= 1) {
        int n = __shfl_up_sync(0xffffffffu, sc, off);
        if (lane >= off) sc += n;
    }
    if (lane == 31) wsum[wd] = sc;
    __syncthreads();
    int woff = 0;
#pragma unroll
    for (int i = 0; i < 8; i++) woff += (i < wd) ? wsum[i] : 0;
    int w = woff + sc - c;   // exclusive prefix
    float4* lg4 = ((float4*)logits) + b * NS;
    const float4 fill = make_float4(-NEG_BIG, -NEG_BIG, -NEG_BIG, -NEG_BIG);
#pragma unroll
    for (int i = 0; i < 16; i++) {
        if (m[i]) g_idx[b * NS + (w++)] = base + i;
        else lg4[base + i] = fill;
    }
    if (tid == 255) g_cnt[b] = w;
}

// ---------------------------------------------------------------------------
// K1: persistent bf16-split mma.sync (x@Wk) -> tanh -> @Wo on COMPACTED rows.
// ---------------------------------------------------------------------------
__global__ __launch_bounds__(256, 1) void k1_mma_kernel(
    const float* __restrict__ x,
    const float* __restrict__ Wk, const float* __restrict__ Wo,
    float* __restrict__ logits)
{
    extern __shared__ char smem[];
    const int tid  = threadIdx.x;
    const int wid  = tid >> 5;
    const int lane = tid & 31;
    const int g    = lane >> 2;
    const int t    = lane & 3;
    const int p    = wid >> 1;      // pair 0..3
    const int nw   = wid & 1;
    const int qp   = tid & 63;

    int* tk = (int*)(smem + OFF_TK);
    float4* wo4s = (float4*)(smem + OFF_WO);
    if (tid < 128) wo4s[tid] = ((const float4*)Wo)[tid];

    // B fragments (Wk split hi/lo, mma-fragment order)
    for (int s = tid; s < 4096; s += 256) {
        int sl = s & 31, sg = sl >> 2, st = sl & 3;
        int idx = s >> 5, ks = idx >> 4, nt = idx & 15;
        int n = nt * 8 + sg;
        int k0 = ks * 16 + st * 2;
        float v00 = Wk[k0 * 128 + n];
        float v01 = Wk[k0 * 128 + 128 + n];
        float v10 = Wk[(k0 + 8) * 128 + n];
        float v11 = Wk[(k0 + 9) * 128 + n];
        uint32_t b0h, b0l, b1h, b1l;
        split2(v00, v01, b0h, b0l);
        split2(v10, v11, b1h, b1l);
        uint4 u; u.x = b0h; u.y = b1h; u.z = b0l; u.w = b1l;
        *(uint4*)(smem + OFF_B + s * 16) = u;
    }
    __syncthreads();

    const float4* xg4 = (const float4*)x;
    float4* pedbase = (float4*)(smem + OFF_PED);

    if (nw == 0 && lane == 0) tk[p] = grab_slot();
    PAIR_BAR(1 + p);
    int slot = tk[p];

    if (slot >= 0) {
        int b = slot >> 7, u = slot & 127, cnt = g_cnt[b];
        const int* ib = g_idx + b * NS;
        char* dst = smem + OFF_A + (p * 2) * ASZ;
#pragma unroll
        for (int i = 0; i < 16; i++) {
            int idx = qp + 64 * i;
            int row = idx >> 5, c4 = idx & 31;
            int j = u * 32 + row; if (j > cnt - 1) j = cnt - 1;
            int s = ib[j];
            float4 v = xg4[((size_t)b * NS + s) * 32 + c4];
            uint32_t h0, l0, h1, l1;
            split2(v.x, v.y, h0, l0);
            split2(v.z, v.w, h1, l1);
            uint4 uu; uu.x = h0; uu.y = l0; uu.z = h1; uu.w = l1;
            *(uint4*)(dst + row * APITCH + c4 * 16) = uu;
        }
        if (nw == 0 && lane == 0) tk[p] = grab_slot();
    }
    PAIR_BAR(1 + p);
    int nslot = (slot >= 0) ? tk[p] : -1;

    int buf = 0;
    while (slot >= 0) {
        const int b = slot >> 7, u = slot & 127;

        float4 xr[16];
        if (nslot >= 0) {
            int bn = nslot >> 7, un = nslot & 127, cntn = g_cnt[bn];
            const int* ibn = g_idx + bn * NS;
#pragma unroll
            for (int i = 0; i < 16; i++) {
                int idx = qp + 64 * i;
                int row = idx >> 5, c4 = idx & 31;
                int j = un * 32 + row; if (j > cntn - 1) j = cntn - 1;
                int s = ibn[j];
                xr[i] = xg4[((size_t)bn * NS + s) * 32 + c4];
            }
        }

        const char* Abuf = smem + OFF_A + (p * 2 + buf) * ASZ;
        float acc[2][8][4];
#pragma unroll
        for (int mt = 0; mt < 2; mt++)
#pragma unroll
            for (int nt = 0; nt < 8; nt++)
#pragma unroll
                for (int c = 0; c < 4; c++) acc[mt][nt][c] = 0.0f;

#pragma unroll
        for (int ks = 0; ks < 8; ks++) {
            uint4 B[8];
#pragma unroll
            for (int nt = 0; nt < 8; nt++)
                B[nt] = *(const uint4*)(smem + OFF_B +
                        (((ks * 16) + (nw * 8 + nt)) * 32 + lane) * 16);
#pragma unroll
            for (int mt = 0; mt < 2; mt++) {
                const char* Ar = Abuf + mt * 16 * APITCH;
                int pk = ks * 8 + t;
                uint2 ax0 = *(const uint2*)(Ar + g * APITCH + pk * 8);
                uint2 ax1 = *(const uint2*)(Ar + (g + 8) * APITCH + pk * 8);
                uint2 ax2 = *(const uint2*)(Ar + g * APITCH + (pk + 4) * 8);
                uint2 ax3 = *(const uint2*)(Ar + (g + 8) * APITCH + (pk + 4) * 8);
#pragma unroll
                for (int nt = 0; nt < 8; nt++)
                    mma16816(acc[mt][nt], ax0.x, ax1.x, ax2.x, ax3.x,
                             B[nt].x, B[nt].y);
#pragma unroll
                for (int nt = 0; nt < 8; nt++)
                    mma16816(acc[mt][nt], ax0.y, ax1.y, ax2.y, ax3.y,
                             B[nt].x, B[nt].y);
#pragma unroll
                for (int nt = 0; nt < 8; nt++)
                    mma16816(acc[mt][nt], ax0.x, ax1.x, ax2.x, ax3.x,
                             B[nt].z, B[nt].w);
            }
        }

        float hp[4][4];
#pragma unroll
        for (int r = 0; r < 4; r++)
#pragma unroll
            for (int h = 0; h < 4; h++) hp[r][h] = 0.0f;

#pragma unroll
        for (int nt = 0; nt < 8; nt++) {
            int col = nw * 64 + nt * 8 + 2 * t;
            float4 w0 = wo4s[col];
            float4 w1 = wo4s[col + 1];
#pragma unroll
            for (int mt = 0; mt < 2; mt++) {
                float* c = acc[mt][nt];
                float t0 = fast_tanh(c[0]);
                float t1 = fast_tanh(c[1]);
                float t2 = fast_tanh(c[2]);
                float t3 = fast_tanh(c[3]);
                int r0 = mt * 2, r1 = mt * 2 + 1;
                hp[r0][0] = fmaf(t0, w0.x, fmaf(t1, w1.x, hp[r0][0]));
                hp[r0][1] = fmaf(t0, w0.y, fmaf(t1, w1.y, hp[r0][1]));
                hp[r0][2] = fmaf(t0, w0.z, fmaf(t1, w1.z, hp[r0][2]));
                hp[r0][3] = fmaf(t0, w0.w, fmaf(t1, w1.w, hp[r0][3]));
                hp[r1][0] = fmaf(t2, w0.x, fmaf(t3, w1.x, hp[r1][0]));
                hp[r1][1] = fmaf(t2, w0.y, fmaf(t3, w1.y, hp[r1][1]));
                hp[r1][2] = fmaf(t2, w0.z, fmaf(t3, w1.z, hp[r1][2]));
                hp[r1][3] = fmaf(t2, w0.w, fmaf(t3, w1.w, hp[r1][3]));
            }
        }
#pragma unroll
        for (int off = 1; off <= 2; off <<= 1)
#pragma unroll
            for (int r = 0; r < 4; r++)
#pragma unroll
                for (int h = 0; h < 4; h++)
                    hp[r][h] += __shfl_xor_sync(0xffffffffu, hp[r][h], off);

        float4* pedp = pedbase + (p * 2 + buf) * 64;
        if (t == 0) {
            pedp[nw * 32 + g]      = make_float4(hp[0][0], hp[0][1], hp[0][2], hp[0][3]);
            pedp[nw * 32 + 8 + g]  = make_float4(hp[1][0], hp[1][1], hp[1][2], hp[1][3]);
            pedp[nw * 32 + 16 + g] = make_float4(hp[2][0], hp[2][1], hp[2][2], hp[2][3]);
            pedp[nw * 32 + 24 + g] = make_float4(hp[3][0], hp[3][1], hp[3][2], hp[3][3]);
        }

        if (nslot >= 0) {
            char* dst = smem + OFF_A + (p * 2 + (1 - buf)) * ASZ;
#pragma unroll
            for (int i = 0; i < 16; i++) {
                int idx = qp + 64 * i;
                int row = idx >> 5, c4 = idx & 31;
                uint32_t h0, l0, h1, l1;
                split2(xr[i].x, xr[i].y, h0, l0);
                split2(xr[i].z, xr[i].w, h1, l1);
                uint4 uu; uu.x = h0; uu.y = l0; uu.z = h1; uu.w = l1;
                *(uint4*)(dst + row * APITCH + c4 * 16) = uu;
            }
            if (nw == 0 && lane == 0) tk[p] = grab_slot();
        }

        PAIR_BAR(1 + p);

        if (nw == 0) {
            int cnt = g_cnt[b];
            int j = u * 32 + lane;
            if (j < cnt) {
                float4 a = pedp[lane];
                float4 bb = pedp[32 + lane];
                int s = g_idx[b * NS + j];
                float4 o;
                o.x = a.x + bb.x; o.y = a.y + bb.y;
                o.z = a.z + bb.z; o.w = a.w + bb.w;
                ((float4*)logits)[b * NS + s] = o;
            }
        }

        slot = nslot;
        nslot = (slot >= 0) ? tk[p] : -1;
        buf ^= 1;
    }
}

// ---------------------------------------------------------------------------
// K2: in-place softmax over S for each (b, h). One block per b.
// ---------------------------------------------------------------------------
__global__ __launch_bounds__(256) void k2_kernel(float* __restrict__ w)
{
    __shared__ float red[8][4];
    __shared__ float bc[4];
    const int b = blockIdx.x, tid = threadIdx.x;
    const int lane = tid & 31, wid = tid >> 5;

    float4* p = ((float4*)w) + b * NS;
    float4 v[16];
#pragma unroll
    for (int i = 0; i < 16; i++) v[i] = p[tid + 256 * i];

    float m0 = -3.4e38f, m1 = m0, m2 = m0, m3 = m0;
#pragma unroll
    for (int i = 0; i < 16; i++) {
        m0 = fmaxf(m0, v[i].x); m1 = fmaxf(m1, v[i].y);
        m2 = fmaxf(m2, v[i].z); m3 = fmaxf(m3, v[i].w);
    }
#pragma unroll
    for (int off = 16; off >= 1; off >>= 1) {
        m0 = fmaxf(m0, __shfl_xor_sync(0xffffffffu, m0, off));
        m1 = fmaxf(m1, __shfl_xor_sync(0xffffffffu, m1, off));
        m2 = fmaxf(m2, __shfl_xor_sync(0xffffffffu, m2, off));
        m3 = fmaxf(m3, __shfl_xor_sync(0xffffffffu, m3, off));
    }
    if (lane == 0) { red[wid][0] = m0; red[wid][1] = m1; red[wid][2] = m2; red[wid][3] = m3; }
    __syncthreads();
    if (tid < 4) {
        float m = red[0][tid];
#pragma unroll
        for (int i = 1; i < 8; i++) m = fmaxf(m, red[i][tid]);
        bc[tid] = m;
    }
    __syncthreads();
    m0 = bc[0]; m1 = bc[1]; m2 = bc[2]; m3 = bc[3];

    float s0 = 0.f, s1 = 0.f, s2 = 0.f, s3 = 0.f;
#pragma unroll
    for (int i = 0; i < 16; i++) {
        v[i].x = __expf(v[i].x - m0); s0 += v[i].x;
        v[i].y = __expf(v[i].y - m1); s1 += v[i].y;
        v[i].z = __expf(v[i].z - m2); s2 += v[i].z;
        v[i].w = __expf(v[i].w - m3); s3 += v[i].w;
    }
#pragma unroll
    for (int off = 16; off >= 1; off >>= 1) {
        s0 += __shfl_xor_sync(0xffffffffu, s0, off);
        s1 += __shfl_xor_sync(0xffffffffu, s1, off);
        s2 += __shfl_xor_sync(0xffffffffu, s2, off);
        s3 += __shfl_xor_sync(0xffffffffu, s3, off);
    }
    if (lane == 0) { red[wid][0] = s0; red[wid][1] = s1; red[wid][2] = s2; red[wid][3] = s3; }
    __syncthreads();
    if (tid < 4) {
        float s = 0.f;
#pragma unroll
        for (int i = 0; i < 8; i++) s += red[i][tid];
        bc[tid] = 1.0f / s;
    }
    __syncthreads();
    s0 = bc[0]; s1 = bc[1]; s2 = bc[2]; s3 = bc[3];
#pragma unroll
    for (int i = 0; i < 16; i++) {
        v[i].x *= s0; v[i].y *= s1; v[i].z *= s2; v[i].w *= s3;
        p[tid + 256 * i] = v[i];
    }
}

// ---------------------------------------------------------------------------
// K3: gather-pooling over compacted rows (r5 simple loop), grid (16, NB)
// for occupancy, + per-batch final reduction folded in (fixed-order sum).
// ---------------------------------------------------------------------------
__global__ __launch_bounds__(512) void k3_kernel(
    const float* __restrict__ x, const float* __restrict__ w,
    float* __restrict__ part, float* __restrict__ pooled)
{
    __shared__ float sm[16][512];
    __shared__ int isLast;
    const int q = blockIdx.x;    // 0..15
    const int b = blockIdx.y;
    const int tid = threadIdx.x;
    const int d4 = tid & 31;
    const int sg = tid >> 5;

    const int cnt = g_cnt[b];
    const int* ib = g_idx + b * NS;
    const float4* wp = ((const float4*)w) + b * NS;
    const float4* xp = ((const float4*)x) + (size_t)b * NS * 32;

    float a[4][4];
#pragma unroll
    for (int h = 0; h < 4; h++)
#pragma unroll
        for (int j = 0; j < 4; j++) a[h][j] = 0.0f;

    for (int j = q * 16 + sg; j < cnt; j += 256) {
        int s = ib[j];
        float4 wv = wp[s];
        float4 xv = xp[(size_t)s * 32 + d4];
        a[0][0] = fmaf(wv.x, xv.x, a[0][0]); a[0][1] = fmaf(wv.x, xv.y, a[0][1]);
        a[0][2] = fmaf(wv.x, xv.z, a[0][2]); a[0][3] = fmaf(wv.x, xv.w, a[0][3]);
        a[1][0] = fmaf(wv.y, xv.x, a[1][0]); a[1][1] = fmaf(wv.y, xv.y, a[1][1]);
        a[1][2] = fmaf(wv.y, xv.z, a[1][2]); a[1][3] = fmaf(wv.y, xv.w, a[1][3]);
        a[2][0] = fmaf(wv.z, xv.x, a[2][0]); a[2][1] = fmaf(wv.z, xv.y, a[2][1]);
        a[2][2] = fmaf(wv.z, xv.z, a[2][2]); a[2][3] = fmaf(wv.z, xv.w, a[2][3]);
        a[3][0] = fmaf(wv.w, xv.x, a[3][0]); a[3][1] = fmaf(wv.w, xv.y, a[3][1]);
        a[3][2] = fmaf(wv.w, xv.z, a[3][2]); a[3][3] = fmaf(wv.w, xv.w, a[3][3]);
    }
#pragma unroll
    for (int h = 0; h < 4; h++)
#pragma unroll
        for (int j = 0; j < 4; j++)
            sm[sg][h * 128 + d4 * 4 + j] = a[h][j];
    __syncthreads();

    float ssum = 0.0f;
#pragma unroll
    for (int gi = 0; gi < 16; gi++) ssum += sm[gi][tid];
    part[(q * NB + b) * 512 + tid] = ssum;

    // per-batch final combine: last of the 16 blocks for batch b sums q=0..15
    __threadfence();
    if (tid == 0) {
        int old = atomicAdd(&g_done[b], 1);
        isLast = (old == 15);
    }
    __syncthreads();
    if (isLast) {
        float s = 0.0f;
#pragma unroll
        for (int k = 0; k < 16; k++)
            s += __ldcg(&part[(k * NB + b) * 512 + tid]);
        pooled[b * 512 + tid] = s;
    }
}

// ---------------------------------------------------------------------------
extern "C" void kernel_launch(void* const* d_in, const int* in_sizes, int n_in,
                              void* d_out, int out_size)
{
    const float* x   = (const float*)d_in[0];
    const int*   msk = (const int*)d_in[1];
    const float* Wk  = (const float*)d_in[2];
    const float* Wo  = (const float*)d_in[3];
    float* out = (float*)d_out;

    const int pooled_elems = NB * NH * ND;   // 16384
    const int w_elems = NB * NS * NH;        // 524288

    float* pooled = out;
    float* wbuf;
    if (out_size >= pooled_elems + w_elems) {
        wbuf = out + pooled_elems;
    } else {
        void* p = nullptr;
        cudaGetSymbolAddress(&p, g_w_scratch);
        wbuf = (float*)p;
    }

    cudaFuncSetAttribute(k1_mma_kernel,
                         cudaFuncAttributeMaxDynamicSharedMemorySize, SMEM_K1);

    k0_compact<<<NB, 256>>>(msk, wbuf);
    k1_mma_kernel<<<GRID1, 256, SMEM_K1>>>(x, Wk, Wo, wbuf);
    k2_kernel<<<NB, 256>>>(wbuf);

    void* pp = nullptr;
    cudaGetSymbolAddress(&pp, g_part);
    k3_kernel<<<dim3(16, NB), 512>>>(x, wbuf, (float*)pp, pooled);
}

// round 10
// speedup vs baseline: 1.1974x; 1.0712x over previous
#include <cuda_runtime.h>
#include <cstdint>

#define NEG_BIG 1e12f
#define NB 32
#define NS 4096
#define ND 128
#define NH 4
#define NROWS (NB * NS)       // 131072
#define GRID1 148
#define NSLOTS (NB * 128)     // 128 32-row unit slots per batch

// scratch
__device__ float g_w_scratch[NB * NS * NH];   // 2 MB fallback
__device__ float g_part[8 * NB * NH * ND];    // 512 KB partials
__device__ int   g_idx[NB * NS];              // compacted row indices per batch
__device__ int   g_cnt[NB];                   // unmasked count per batch
__device__ int   g_ticket;                    // dynamic work ticket

// ---------------------------------------------------------------------------
// SMEM layout for k1 (bytes)
// ---------------------------------------------------------------------------
#define OFF_B    0                 // B fragments: 4096 slots x 16B = 65536
#define OFF_WO   65536             // 2048
#define OFF_PED  67584             // 4 pairs x 2 bufs x 64 float4 = 8192
#define OFF_TK   75776             // 4 ints (+pad to 64)
#define OFF_A    75840             // 8 x (32 rows x APITCH)
#define APITCH   528
#define ASZ      (32 * APITCH)     // 16896 per (pair,buf)
#define SMEM_K1  (OFF_A + 8 * ASZ) // 211008

// ---------------------------------------------------------------------------
// helpers
// ---------------------------------------------------------------------------
__device__ __forceinline__ void split2(float v0, float v1,
                                       uint32_t& hi, uint32_t& lo) {
    uint32_t u0 = __float_as_uint(v0), u1 = __float_as_uint(v1);
    uint32_t h;
    asm("prmt.b32 %0, %1, %2, 0x7632;" : "=r"(h) : "r"(u0), "r"(u1));
    float r0 = v0 - __uint_as_float(u0 & 0xFFFF0000u);
    float r1 = v1 - __uint_as_float(u1 & 0xFFFF0000u);
    uint32_t l;
    asm("cvt.rn.bf16x2.f32 %0, %1, %2;" : "=r"(l) : "f"(r1), "f"(r0));
    hi = h; lo = l;
}

__device__ __forceinline__ void mma16816(float* c,
    uint32_t a0, uint32_t a1, uint32_t a2, uint32_t a3,
    uint32_t b0, uint32_t b1)
{
    asm volatile(
        "mma.sync.aligned.m16n8k16.row.col.f32.bf16.bf16.f32 "
        "{%0,%1,%2,%3}, {%4,%5,%6,%7}, {%8,%9}, {%0,%1,%2,%3};"
        : "+f"(c[0]), "+f"(c[1]), "+f"(c[2]), "+f"(c[3])
        : "r"(a0), "r"(a1), "r"(a2), "r"(a3), "r"(b0), "r"(b1));
}

__device__ __forceinline__ float fast_tanh(float a) {
    float r;
    asm("tanh.approx.f32 %0, %1;" : "=f"(r) : "f"(a));
    return r;
}

#define PAIR_BAR(id) asm volatile("bar.sync %0, 64;" :: "r"(id) : "memory")

__device__ __forceinline__ int grab_slot() {
    for (;;) {
        int s = atomicAdd(&g_ticket, 1);
        if (s >= NSLOTS) return -1;
        int b = s >> 7, u = s & 127;
        if (u * 32 < g_cnt[b]) return s;
    }
}

// ---------------------------------------------------------------------------
// K0: per-batch order-preserving compaction of unmasked row indices +
// fill masked logits with -1e12 (so k2's softmax zeroes them exactly).
// ---------------------------------------------------------------------------
__global__ __launch_bounds__(256) void k0_compact(
    const int* __restrict__ mask, float* __restrict__ logits)
{
    __shared__ int wsum[8];
    const int b = blockIdx.x, tid = threadIdx.x;
    if (b == 0 && tid == 0) g_ticket = 0;
    const int base = tid * 16;
    const int* mb = mask + b * NS;
    int m[16], c = 0;
#pragma unroll
    for (int i = 0; i < 16; i++) { m[i] = mb[base + i]; c += m[i]; }
    const int lane = tid & 31, wd = tid >> 5;
    int sc = c;
#pragma unroll
    for (int off = 1; off < 32; off <<= 1) {
        int n = __shfl_up_sync(0xffffffffu, sc, off);
        if (lane >= off) sc += n;
    }
    if (lane == 31) wsum[wd] = sc;
    __syncthreads();
    int woff = 0;
#pragma unroll
    for (int i = 0; i < 8; i++) woff += (i < wd) ? wsum[i] : 0;
    int w = woff + sc - c;   // exclusive prefix
    float4* lg4 = ((float4*)logits) + b * NS;
    const float4 fill = make_float4(-NEG_BIG, -NEG_BIG, -NEG_BIG, -NEG_BIG);
#pragma unroll
    for (int i = 0; i < 16; i++) {
        if (m[i]) g_idx[b * NS + (w++)] = base + i;
        else lg4[base + i] = fill;
    }
    if (tid == 255) g_cnt[b] = w;
}

// ---------------------------------------------------------------------------
// K1: persistent bf16-split mma.sync (x@Wk) -> tanh -> @Wo on COMPACTED rows.
// ---------------------------------------------------------------------------
__global__ __launch_bounds__(256, 1) void k1_mma_kernel(
    const float* __restrict__ x,
    const float* __restrict__ Wk, const float* __restrict__ Wo,
    float* __restrict__ logits)
{
    extern __shared__ char smem[];
    const int tid  = threadIdx.x;
    const int wid  = tid >> 5;
    const int lane = tid & 31;
    const int g    = lane >> 2;
    const int t    = lane & 3;
    const int p    = wid >> 1;      // pair 0..3
    const int nw   = wid & 1;
    const int qp   = tid & 63;

    int* tk = (int*)(smem + OFF_TK);
    float4* wo4s = (float4*)(smem + OFF_WO);
    if (tid < 128) wo4s[tid] = ((const float4*)Wo)[tid];

    // B fragments (Wk split hi/lo, mma-fragment order)
    for (int s = tid; s < 4096; s += 256) {
        int sl = s & 31, sg = sl >> 2, st = sl & 3;
        int idx = s >> 5, ks = idx >> 4, nt = idx & 15;
        int n = nt * 8 + sg;
        int k0 = ks * 16 + st * 2;
        float v00 = Wk[k0 * 128 + n];
        float v01 = Wk[k0 * 128 + 128 + n];
        float v10 = Wk[(k0 + 8) * 128 + n];
        float v11 = Wk[(k0 + 9) * 128 + n];
        uint32_t b0h, b0l, b1h, b1l;
        split2(v00, v01, b0h, b0l);
        split2(v10, v11, b1h, b1l);
        uint4 u; u.x = b0h; u.y = b1h; u.z = b0l; u.w = b1l;
        *(uint4*)(smem + OFF_B + s * 16) = u;
    }
    __syncthreads();

    const float4* xg4 = (const float4*)x;
    float4* pedbase = (float4*)(smem + OFF_PED);

    if (nw == 0 && lane == 0) tk[p] = grab_slot();
    PAIR_BAR(1 + p);
    int slot = tk[p];

    if (slot >= 0) {
        int b = slot >> 7, u = slot & 127, cnt = g_cnt[b];
        const int* ib = g_idx + b * NS;
        char* dst = smem + OFF_A + (p * 2) * ASZ;
#pragma unroll
        for (int i = 0; i < 16; i++) {
            int idx = qp + 64 * i;
            int row = idx >> 5, c4 = idx & 31;
            int j = u * 32 + row; if (j > cnt - 1) j = cnt - 1;
            int s = ib[j];
            float4 v = xg4[((size_t)b * NS + s) * 32 + c4];
            uint32_t h0, l0, h1, l1;
            split2(v.x, v.y, h0, l0);
            split2(v.z, v.w, h1, l1);
            uint4 uu; uu.x = h0; uu.y = l0; uu.z = h1; uu.w = l1;
            *(uint4*)(dst + row * APITCH + c4 * 16) = uu;
        }
        if (nw == 0 && lane == 0) tk[p] = grab_slot();
    }
    PAIR_BAR(1 + p);
    int nslot = (slot >= 0) ? tk[p] : -1;

    int buf = 0;
    while (slot >= 0) {
        const int b = slot >> 7, u = slot & 127;

        float4 xr[16];
        if (nslot >= 0) {
            int bn = nslot >> 7, un = nslot & 127, cntn = g_cnt[bn];
            const int* ibn = g_idx + bn * NS;
#pragma unroll
            for (int i = 0; i < 16; i++) {
                int idx = qp + 64 * i;
                int row = idx >> 5, c4 = idx & 31;
                int j = un * 32 + row; if (j > cntn - 1) j = cntn - 1;
                int s = ibn[j];
                xr[i] = xg4[((size_t)bn * NS + s) * 32 + c4];
            }
        }

        const char* Abuf = smem + OFF_A + (p * 2 + buf) * ASZ;
        float acc[2][8][4];
#pragma unroll
        for (int mt = 0; mt < 2; mt++)
#pragma unroll
            for (int nt = 0; nt < 8; nt++)
#pragma unroll
                for (int c = 0; c < 4; c++) acc[mt][nt][c] = 0.0f;

#pragma unroll
        for (int ks = 0; ks < 8; ks++) {
            uint4 B[8];
#pragma unroll
            for (int nt = 0; nt < 8; nt++)
                B[nt] = *(const uint4*)(smem + OFF_B +
                        (((ks * 16) + (nw * 8 + nt)) * 32 + lane) * 16);
#pragma unroll
            for (int mt = 0; mt < 2; mt++) {
                const char* Ar = Abuf + mt * 16 * APITCH;
                int pk = ks * 8 + t;
                uint2 ax0 = *(const uint2*)(Ar + g * APITCH + pk * 8);
                uint2 ax1 = *(const uint2*)(Ar + (g + 8) * APITCH + pk * 8);
                uint2 ax2 = *(const uint2*)(Ar + g * APITCH + (pk + 4) * 8);
                uint2 ax3 = *(const uint2*)(Ar + (g + 8) * APITCH + (pk + 4) * 8);
#pragma unroll
                for (int nt = 0; nt < 8; nt++)
                    mma16816(acc[mt][nt], ax0.x, ax1.x, ax2.x, ax3.x,
                             B[nt].x, B[nt].y);
#pragma unroll
                for (int nt = 0; nt < 8; nt++)
                    mma16816(acc[mt][nt], ax0.y, ax1.y, ax2.y, ax3.y,
                             B[nt].x, B[nt].y);
#pragma unroll
                for (int nt = 0; nt < 8; nt++)
                    mma16816(acc[mt][nt], ax0.x, ax1.x, ax2.x, ax3.x,
                             B[nt].z, B[nt].w);
            }
        }

        float hp[4][4];
#pragma unroll
        for (int r = 0; r < 4; r++)
#pragma unroll
            for (int h = 0; h < 4; h++) hp[r][h] = 0.0f;

#pragma unroll
        for (int nt = 0; nt < 8; nt++) {
            int col = nw * 64 + nt * 8 + 2 * t;
            float4 w0 = wo4s[col];
            float4 w1 = wo4s[col + 1];
#pragma unroll
            for (int mt = 0; mt < 2; mt++) {
                float* c = acc[mt][nt];
                float t0 = fast_tanh(c[0]);
                float t1 = fast_tanh(c[1]);
                float t2 = fast_tanh(c[2]);
                float t3 = fast_tanh(c[3]);
                int r0 = mt * 2, r1 = mt * 2 + 1;
                hp[r0][0] = fmaf(t0, w0.x, fmaf(t1, w1.x, hp[r0][0]));
                hp[r0][1] = fmaf(t0, w0.y, fmaf(t1, w1.y, hp[r0][1]));
                hp[r0][2] = fmaf(t0, w0.z, fmaf(t1, w1.z, hp[r0][2]));
                hp[r0][3] = fmaf(t0, w0.w, fmaf(t1, w1.w, hp[r0][3]));
                hp[r1][0] = fmaf(t2, w0.x, fmaf(t3, w1.x, hp[r1][0]));
                hp[r1][1] = fmaf(t2, w0.y, fmaf(t3, w1.y, hp[r1][1]));
                hp[r1][2] = fmaf(t2, w0.z, fmaf(t3, w1.z, hp[r1][2]));
                hp[r1][3] = fmaf(t2, w0.w, fmaf(t3, w1.w, hp[r1][3]));
            }
        }
#pragma unroll
        for (int off = 1; off <= 2; off <<= 1)
#pragma unroll
            for (int r = 0; r < 4; r++)
#pragma unroll
                for (int h = 0; h < 4; h++)
                    hp[r][h] += __shfl_xor_sync(0xffffffffu, hp[r][h], off);

        float4* pedp = pedbase + (p * 2 + buf) * 64;
        if (t == 0) {
            pedp[nw * 32 + g]      = make_float4(hp[0][0], hp[0][1], hp[0][2], hp[0][3]);
            pedp[nw * 32 + 8 + g]  = make_float4(hp[1][0], hp[1][1], hp[1][2], hp[1][3]);
            pedp[nw * 32 + 16 + g] = make_float4(hp[2][0], hp[2][1], hp[2][2], hp[2][3]);
            pedp[nw * 32 + 24 + g] = make_float4(hp[3][0], hp[3][1], hp[3][2], hp[3][3]);
        }

        if (nslot >= 0) {
            char* dst = smem + OFF_A + (p * 2 + (1 - buf)) * ASZ;
#pragma unroll
            for (int i = 0; i < 16; i++) {
                int idx = qp + 64 * i;
                int row = idx >> 5, c4 = idx & 31;
                uint32_t h0, l0, h1, l1;
                split2(xr[i].x, xr[i].y, h0, l0);
                split2(xr[i].z, xr[i].w, h1, l1);
                uint4 uu; uu.x = h0; uu.y = l0; uu.z = h1; uu.w = l1;
                *(uint4*)(dst + row * APITCH + c4 * 16) = uu;
            }
            if (nw == 0 && lane == 0) tk[p] = grab_slot();
        }

        PAIR_BAR(1 + p);

        if (nw == 0) {
            int cnt = g_cnt[b];
            int j = u * 32 + lane;
            if (j < cnt) {
                float4 a = pedp[lane];
                float4 bb = pedp[32 + lane];
                int s = g_idx[b * NS + j];
                float4 o;
                o.x = a.x + bb.x; o.y = a.y + bb.y;
                o.z = a.z + bb.z; o.w = a.w + bb.w;
                ((float4*)logits)[b * NS + s] = o;
            }
        }

        slot = nslot;
        nslot = (slot >= 0) ? tk[p] : -1;
        buf ^= 1;
    }
}

// ---------------------------------------------------------------------------
// K2: in-place softmax over S for each (b, h). One block per b, 1024 threads
// (4 float4/thread) for memory parallelism; 32-warp two-stage reduction.
// ---------------------------------------------------------------------------
__global__ __launch_bounds__(1024) void k2_kernel(float* __restrict__ w)
{
    __shared__ float red[32][4];
    __shared__ float bc[4];
    const int b = blockIdx.x, tid = threadIdx.x;
    const int lane = tid & 31, wid = tid >> 5;

    float4* p = ((float4*)w) + b * NS;
    float4 v[4];
#pragma unroll
    for (int i = 0; i < 4; i++) v[i] = p[tid + 1024 * i];

    float m0 = -3.4e38f, m1 = m0, m2 = m0, m3 = m0;
#pragma unroll
    for (int i = 0; i < 4; i++) {
        m0 = fmaxf(m0, v[i].x); m1 = fmaxf(m1, v[i].y);
        m2 = fmaxf(m2, v[i].z); m3 = fmaxf(m3, v[i].w);
    }
#pragma unroll
    for (int off = 16; off >= 1; off >>= 1) {
        m0 = fmaxf(m0, __shfl_xor_sync(0xffffffffu, m0, off));
        m1 = fmaxf(m1, __shfl_xor_sync(0xffffffffu, m1, off));
        m2 = fmaxf(m2, __shfl_xor_sync(0xffffffffu, m2, off));
        m3 = fmaxf(m3, __shfl_xor_sync(0xffffffffu, m3, off));
    }
    if (lane == 0) { red[wid][0] = m0; red[wid][1] = m1; red[wid][2] = m2; red[wid][3] = m3; }
    __syncthreads();
    if (tid < 4) {
        float m = red[0][tid];
#pragma unroll
        for (int i = 1; i < 32; i++) m = fmaxf(m, red[i][tid]);
        bc[tid] = m;
    }
    __syncthreads();
    m0 = bc[0]; m1 = bc[1]; m2 = bc[2]; m3 = bc[3];

    float s0 = 0.f, s1 = 0.f, s2 = 0.f, s3 = 0.f;
#pragma unroll
    for (int i = 0; i < 4; i++) {
        v[i].x = __expf(v[i].x - m0); s0 += v[i].x;
        v[i].y = __expf(v[i].y - m1); s1 += v[i].y;
        v[i].z = __expf(v[i].z - m2); s2 += v[i].z;
        v[i].w = __expf(v[i].w - m3); s3 += v[i].w;
    }
#pragma unroll
    for (int off = 16; off >= 1; off >>= 1) {
        s0 += __shfl_xor_sync(0xffffffffu, s0, off);
        s1 += __shfl_xor_sync(0xffffffffu, s1, off);
        s2 += __shfl_xor_sync(0xffffffffu, s2, off);
        s3 += __shfl_xor_sync(0xffffffffu, s3, off);
    }
    if (lane == 0) { red[wid][0] = s0; red[wid][1] = s1; red[wid][2] = s2; red[wid][3] = s3; }
    __syncthreads();
    if (tid < 4) {
        float s = 0.f;
#pragma unroll
        for (int i = 0; i < 32; i++) s += red[i][tid];
        bc[tid] = 1.0f / s;
    }
    __syncthreads();
    s0 = bc[0]; s1 = bc[1]; s2 = bc[2]; s3 = bc[3];
#pragma unroll
    for (int i = 0; i < 4; i++) {
        v[i].x *= s0; v[i].y *= s1; v[i].z *= s2; v[i].w *= s3;
        p[tid + 1024 * i] = v[i];
    }
}

// ---------------------------------------------------------------------------
// K3: gather-pooling over compacted rows. Grid (8, 32), 512 threads.
// (EXACT r5 source — proven 12.6 us; do not perturb.)
// ---------------------------------------------------------------------------
__global__ __launch_bounds__(512) void k3_kernel(
    const float* __restrict__ x, const float* __restrict__ w,
    float* __restrict__ part)
{
    __shared__ float sm[16][512];
    const int q = blockIdx.x;    // 0..7
    const int b = blockIdx.y;
    const int tid = threadIdx.x;
    const int d4 = tid & 31;
    const int sg = tid >> 5;

    const int cnt = g_cnt[b];
    const int* ib = g_idx + b * NS;
    const float4* wp = ((const float4*)w) + b * NS;
    const float4* xp = ((const float4*)x) + (size_t)b * NS * 32;

    float a[4][4];
#pragma unroll
    for (int h = 0; h < 4; h++)
#pragma unroll
        for (int j = 0; j < 4; j++) a[h][j] = 0.0f;

    for (int j = q * 16 + sg; j < cnt; j += 128) {
        int s = ib[j];
        float4 wv = wp[s];
        float4 xv = xp[(size_t)s * 32 + d4];
        a[0][0] = fmaf(wv.x, xv.x, a[0][0]); a[0][1] = fmaf(wv.x, xv.y, a[0][1]);
        a[0][2] = fmaf(wv.x, xv.z, a[0][2]); a[0][3] = fmaf(wv.x, xv.w, a[0][3]);
        a[1][0] = fmaf(wv.y, xv.x, a[1][0]); a[1][1] = fmaf(wv.y, xv.y, a[1][1]);
        a[1][2] = fmaf(wv.y, xv.z, a[1][2]); a[1][3] = fmaf(wv.y, xv.w, a[1][3]);
        a[2][0] = fmaf(wv.z, xv.x, a[2][0]); a[2][1] = fmaf(wv.z, xv.y, a[2][1]);
        a[2][2] = fmaf(wv.z, xv.z, a[2][2]); a[2][3] = fmaf(wv.z, xv.w, a[2][3]);
        a[3][0] = fmaf(wv.w, xv.x, a[3][0]); a[3][1] = fmaf(wv.w, xv.y, a[3][1]);
        a[3][2] = fmaf(wv.w, xv.z, a[3][2]); a[3][3] = fmaf(wv.w, xv.w, a[3][3]);
    }
#pragma unroll
    for (int h = 0; h < 4; h++)
#pragma unroll
        for (int j = 0; j < 4; j++)
            sm[sg][h * 128 + d4 * 4 + j] = a[h][j];
    __syncthreads();

    float ssum = 0.0f;
#pragma unroll
    for (int gi = 0; gi < 16; gi++) ssum += sm[gi][tid];
    part[(q * NB + b) * 512 + tid] = ssum;
}

// K4: combine 8 partials -> pooled [B][H][D]
__global__ __launch_bounds__(256) void k4_kernel(
    const float* __restrict__ part, float* __restrict__ pooled)
{
    int i = blockIdx.x * 256 + threadIdx.x;
    float s = 0.0f;
#pragma unroll
    for (int k = 0; k < 8; k++) s += part[k * 16384 + i];
    pooled[i] = s;
}

// ---------------------------------------------------------------------------
extern "C" void kernel_launch(void* const* d_in, const int* in_sizes, int n_in,
                              void* d_out, int out_size)
{
    const float* x   = (const float*)d_in[0];
    const int*   msk = (const int*)d_in[1];
    const float* Wk  = (const float*)d_in[2];
    const float* Wo  = (const float*)d_in[3];
    float* out = (float*)d_out;

    const int pooled_elems = NB * NH * ND;   // 16384
    const int w_elems = NB * NS * NH;        // 524288

    float* pooled = out;
    float* wbuf;
    if (out_size >= pooled_elems + w_elems) {
        wbuf = out + pooled_elems;
    } else {
        void* p = nullptr;
        cudaGetSymbolAddress(&p, g_w_scratch);
        wbuf = (float*)p;
    }

    cudaFuncSetAttribute(k1_mma_kernel,
                         cudaFuncAttributeMaxDynamicSharedMemorySize, SMEM_K1);

    k0_compact<<<NB, 256>>>(msk, wbuf);
    k1_mma_kernel<<<GRID1, 256, SMEM_K1>>>(x, Wk, Wo, wbuf);
    k2_kernel<<<NB, 1024>>>(wbuf);

    void* pp = nullptr;
    cudaGetSymbolAddress(&pp, g_part);
    k3_kernel<<<dim3(8, NB), 512>>>(x, wbuf, (float*)pp);
    k4_kernel<<<pooled_elems / 256, 256>>>((const float*)pp, pooled);
}

// round 12
// speedup vs baseline: 1.2995x; 1.0853x over previous
#include <cuda_runtime.h>
#include <cstdint>

#define NEG_BIG 1e12f
#define NB 32
#define NS 4096
#define ND 128
#define NH 4
#define NROWS (NB * NS)       // 131072
#define GRID1 148
#define NSLOTS (NB * 128)     // 128 32-row unit slots per batch

// scratch
__device__ float g_w_scratch[NB * NS * NH];   // 2 MB fallback
__device__ float g_part[8 * NB * NH * ND];    // 512 KB partials
__device__ int   g_idx[NB * NS];              // compacted row indices per batch
__device__ int   g_cnt[NB];                   // unmasked count per batch
__device__ int   g_ticket;                    // dynamic work ticket
__device__ uint4 g_bfrag[4096];               // prebuilt Wk hi/lo mma fragments

// ---------------------------------------------------------------------------
// SMEM layout for k1 (bytes) — identical to the 51.7us build
// ---------------------------------------------------------------------------
#define OFF_B    0                 // B fragments: 4096 slots x 16B = 65536
#define OFF_WO   65536             // 2048
#define OFF_PED  67584             // 4 pairs x 2 bufs x 64 float4 = 8192
#define OFF_TK   75776             // 4 ints (+pad to 64)
#define OFF_A    75840             // 8 x (32 rows x APITCH)
#define APITCH   528
#define ASZ      (32 * APITCH)     // 16896 per (pair,buf)
#define SMEM_K1  (OFF_A + 8 * ASZ) // 211008

// ---------------------------------------------------------------------------
// helpers
// ---------------------------------------------------------------------------
// split two f32 into packed bf16x2 hi (truncated) + bf16x2 lo (rounded residual)
__device__ __forceinline__ void split2(float v0, float v1,
                                       uint32_t& hi, uint32_t& lo) {
    uint32_t u0 = __float_as_uint(v0), u1 = __float_as_uint(v1);
    uint32_t h;
    asm("prmt.b32 %0, %1, %2, 0x7632;" : "=r"(h) : "r"(u0), "r"(u1));
    float r0 = v0 - __uint_as_float(u0 & 0xFFFF0000u);
    float r1 = v1 - __uint_as_float(u1 & 0xFFFF0000u);
    uint32_t l;
    asm("cvt.rn.bf16x2.f32 %0, %1, %2;" : "=r"(l) : "f"(r1), "f"(r0));
    hi = h; lo = l;
}

__device__ __forceinline__ void mma16816(float* c,
    uint32_t a0, uint32_t a1, uint32_t a2, uint32_t a3,
    uint32_t b0, uint32_t b1)
{
    asm volatile(
        "mma.sync.aligned.m16n8k16.row.col.f32.bf16.bf16.f32 "
        "{%0,%1,%2,%3}, {%4,%5,%6,%7}, {%8,%9}, {%0,%1,%2,%3};"
        : "+f"(c[0]), "+f"(c[1]), "+f"(c[2]), "+f"(c[3])
        : "r"(a0), "r"(a1), "r"(a2), "r"(a3), "r"(b0), "r"(b1));
}

__device__ __forceinline__ float fast_tanh(float a) {
    float r;
    asm("tanh.approx.f32 %0, %1;" : "=f"(r) : "f"(a));
    return r;
}

#define PAIR_BAR(id) asm volatile("bar.sync %0, 64;" :: "r"(id) : "memory")

__device__ __forceinline__ int grab_slot() {
    for (;;) {
        int s = atomicAdd(&g_ticket, 1);
        if (s >= NSLOTS) return -1;
        int b = s >> 7, u = s & 127;
        if (u * 32 < g_cnt[b]) return s;
    }
}

// ---------------------------------------------------------------------------
// K0: per-batch order-preserving compaction of unmasked row indices +
// fill masked logits with -1e12 + build Wk hi/lo mma fragments (block b
// builds slots [b*128, b*128+128) once, into g_bfrag).
// ---------------------------------------------------------------------------
__global__ __launch_bounds__(256) void k0_compact(
    const int* __restrict__ mask, const float* __restrict__ Wk,
    float* __restrict__ logits)
{
    __shared__ int wsum[8];
    const int b = blockIdx.x, tid = threadIdx.x;
    if (b == 0 && tid == 0) g_ticket = 0;

    // --- B-fragment build: 128 slots per block, threads 0..127 ---
    if (tid < 128) {
        int s = b * 128 + tid;
        int sl = s & 31, sg = sl >> 2, st = sl & 3;
        int idx = s >> 5, ks = idx >> 4, nt = idx & 15;
        int n = nt * 8 + sg;
        int k0 = ks * 16 + st * 2;
        float v00 = Wk[k0 * 128 + n];
        float v01 = Wk[k0 * 128 + 128 + n];
        float v10 = Wk[(k0 + 8) * 128 + n];
        float v11 = Wk[(k0 + 9) * 128 + n];
        uint32_t b0h, b0l, b1h, b1l;
        split2(v00, v01, b0h, b0l);
        split2(v10, v11, b1h, b1l);
        uint4 u; u.x = b0h; u.y = b1h; u.z = b0l; u.w = b1l;
        g_bfrag[s] = u;
    }

    // --- compaction ---
    const int base = tid * 16;
    const int* mb = mask + b * NS;
    int m[16], c = 0;
#pragma unroll
    for (int i = 0; i < 16; i++) { m[i] = mb[base + i]; c += m[i]; }
    const int lane = tid & 31, wd = tid >> 5;
    int sc = c;
#pragma unroll
    for (int off = 1; off < 32; off <<= 1) {
        int n = __shfl_up_sync(0xffffffffu, sc, off);
        if (lane >= off) sc += n;
    }
    if (lane == 31) wsum[wd] = sc;
    __syncthreads();
    int woff = 0;
#pragma unroll
    for (int i = 0; i < 8; i++) woff += (i < wd) ? wsum[i] : 0;
    int w = woff + sc - c;   // exclusive prefix
    float4* lg4 = ((float4*)logits) + b * NS;
    const float4 fill = make_float4(-NEG_BIG, -NEG_BIG, -NEG_BIG, -NEG_BIG);
#pragma unroll
    for (int i = 0; i < 16; i++) {
        if (m[i]) g_idx[b * NS + (w++)] = base + i;
        else lg4[base + i] = fill;
    }
    if (tid == 255) g_cnt[b] = w;
}

// ---------------------------------------------------------------------------
// K1: persistent 3-term bf16-split mma.sync (x@Wk) -> tanh -> @Wo on
// COMPACTED rows. B fragments copied linearly from g_bfrag.
// ---------------------------------------------------------------------------
__global__ __launch_bounds__(256, 1) void k1_mma_kernel(
    const float* __restrict__ x,
    const float* __restrict__ Wo,
    float* __restrict__ logits)
{
    extern __shared__ char smem[];
    const int tid  = threadIdx.x;
    const int wid  = tid >> 5;
    const int lane = tid & 31;
    const int g    = lane >> 2;
    const int t    = lane & 3;
    const int p    = wid >> 1;      // pair 0..3
    const int nw   = wid & 1;
    const int qp   = tid & 63;

    int* tk = (int*)(smem + OFF_TK);
    float4* wo4s = (float4*)(smem + OFF_WO);
    if (tid < 128) wo4s[tid] = ((const float4*)Wo)[tid];

    // B fragments: linear coalesced copy from prebuilt global staging
#pragma unroll
    for (int i = 0; i < 16; i++) {
        int s = tid + 256 * i;
        *(uint4*)(smem + OFF_B + s * 16) = g_bfrag[s];
    }
    __syncthreads();

    const float4* xg4 = (const float4*)x;
    float4* pedbase = (float4*)(smem + OFF_PED);

    if (nw == 0 && lane == 0) tk[p] = grab_slot();
    PAIR_BAR(1 + p);
    int slot = tk[p];

    if (slot >= 0) {
        int b = slot >> 7, u = slot & 127, cnt = g_cnt[b];
        const int* ib = g_idx + b * NS;
        char* dst = smem + OFF_A + (p * 2) * ASZ;
#pragma unroll
        for (int i = 0; i < 16; i++) {
            int idx = qp + 64 * i;
            int row = idx >> 5, c4 = idx & 31;
            int j = u * 32 + row; if (j > cnt - 1) j = cnt - 1;
            int s = ib[j];
            float4 v = xg4[((size_t)b * NS + s) * 32 + c4];
            uint32_t h0, l0, h1, l1;
            split2(v.x, v.y, h0, l0);
            split2(v.z, v.w, h1, l1);
            uint4 uu; uu.x = h0; uu.y = l0; uu.z = h1; uu.w = l1;
            *(uint4*)(dst + row * APITCH + c4 * 16) = uu;
        }
        if (nw == 0 && lane == 0) tk[p] = grab_slot();
    }
    PAIR_BAR(1 + p);
    int nslot = (slot >= 0) ? tk[p] : -1;

    int buf = 0;
    while (slot >= 0) {
        const int b = slot >> 7, u = slot & 127;

        float4 xr[16];
        if (nslot >= 0) {
            int bn = nslot >> 7, un = nslot & 127, cntn = g_cnt[bn];
            const int* ibn = g_idx + bn * NS;
#pragma unroll
            for (int i = 0; i < 16; i++) {
                int idx = qp + 64 * i;
                int row = idx >> 5, c4 = idx & 31;
                int j = un * 32 + row; if (j > cntn - 1) j = cntn - 1;
                int s = ibn[j];
                xr[i] = xg4[((size_t)bn * NS + s) * 32 + c4];
            }
        }

        const char* Abuf = smem + OFF_A + (p * 2 + buf) * ASZ;
        float acc[2][8][4];
#pragma unroll
        for (int mt = 0; mt < 2; mt++)
#pragma unroll
            for (int nt = 0; nt < 8; nt++)
#pragma unroll
                for (int c = 0; c < 4; c++) acc[mt][nt][c] = 0.0f;

#pragma unroll
        for (int ks = 0; ks < 8; ks++) {
            uint4 B[8];
#pragma unroll
            for (int nt = 0; nt < 8; nt++)
                B[nt] = *(const uint4*)(smem + OFF_B +
                        (((ks * 16) + (nw * 8 + nt)) * 32 + lane) * 16);
#pragma unroll
            for (int mt = 0; mt < 2; mt++) {
                const char* Ar = Abuf + mt * 16 * APITCH;
                int pk = ks * 8 + t;
                uint2 ax0 = *(const uint2*)(Ar + g * APITCH + pk * 8);
                uint2 ax1 = *(const uint2*)(Ar + (g + 8) * APITCH + pk * 8);
                uint2 ax2 = *(const uint2*)(Ar + g * APITCH + (pk + 4) * 8);
                uint2 ax3 = *(const uint2*)(Ar + (g + 8) * APITCH + (pk + 4) * 8);
#pragma unroll
                for (int nt = 0; nt < 8; nt++)
                    mma16816(acc[mt][nt], ax0.x, ax1.x, ax2.x, ax3.x,
                             B[nt].x, B[nt].y);
#pragma unroll
                for (int nt = 0; nt < 8; nt++)
                    mma16816(acc[mt][nt], ax0.y, ax1.y, ax2.y, ax3.y,
                             B[nt].x, B[nt].y);
#pragma unroll
                for (int nt = 0; nt < 8; nt++)
                    mma16816(acc[mt][nt], ax0.x, ax1.x, ax2.x, ax3.x,
                             B[nt].z, B[nt].w);
            }
        }

        float hp[4][4];
#pragma unroll
        for (int r = 0; r < 4; r++)
#pragma unroll
            for (int h = 0; h < 4; h++) hp[r][h] = 0.0f;

#pragma unroll
        for (int nt = 0; nt < 8; nt++) {
            int col = nw * 64 + nt * 8 + 2 * t;
            float4 w0 = wo4s[col];
            float4 w1 = wo4s[col + 1];
#pragma unroll
            for (int mt = 0; mt < 2; mt++) {
                float* c = acc[mt][nt];
                float t0 = fast_tanh(c[0]);
                float t1 = fast_tanh(c[1]);
                float t2 = fast_tanh(c[2]);
                float t3 = fast_tanh(c[3]);
                int r0 = mt * 2, r1 = mt * 2 + 1;
                hp[r0][0] = fmaf(t0, w0.x, fmaf(t1, w1.x, hp[r0][0]));
                hp[r0][1] = fmaf(t0, w0.y, fmaf(t1, w1.y, hp[r0][1]));
                hp[r0][2] = fmaf(t0, w0.z, fmaf(t1, w1.z, hp[r0][2]));
                hp[r0][3] = fmaf(t0, w0.w, fmaf(t1, w1.w, hp[r0][3]));
                hp[r1][0] = fmaf(t2, w0.x, fmaf(t3, w1.x, hp[r1][0]));
                hp[r1][1] = fmaf(t2, w0.y, fmaf(t3, w1.y, hp[r1][1]));
                hp[r1][2] = fmaf(t2, w0.z, fmaf(t3, w1.z, hp[r1][2]));
                hp[r1][3] = fmaf(t2, w0.w, fmaf(t3, w1.w, hp[r1][3]));
            }
        }
#pragma unroll
        for (int off = 1; off <= 2; off <<= 1)
#pragma unroll
            for (int r = 0; r < 4; r++)
#pragma unroll
                for (int h = 0; h < 4; h++)
                    hp[r][h] += __shfl_xor_sync(0xffffffffu, hp[r][h], off);

        float4* pedp = pedbase + (p * 2 + buf) * 64;
        if (t == 0) {
            pedp[nw * 32 + g]      = make_float4(hp[0][0], hp[0][1], hp[0][2], hp[0][3]);
            pedp[nw * 32 + 8 + g]  = make_float4(hp[1][0], hp[1][1], hp[1][2], hp[1][3]);
            pedp[nw * 32 + 16 + g] = make_float4(hp[2][0], hp[2][1], hp[2][2], hp[2][3]);
            pedp[nw * 32 + 24 + g] = make_float4(hp[3][0], hp[3][1], hp[3][2], hp[3][3]);
        }

        if (nslot >= 0) {
            char* dst = smem + OFF_A + (p * 2 + (1 - buf)) * ASZ;
#pragma unroll
            for (int i = 0; i < 16; i++) {
                int idx = qp + 64 * i;
                int row = idx >> 5, c4 = idx & 31;
                uint32_t h0, l0, h1, l1;
                split2(xr[i].x, xr[i].y, h0, l0);
                split2(xr[i].z, xr[i].w, h1, l1);
                uint4 uu; uu.x = h0; uu.y = l0; uu.z = h1; uu.w = l1;
                *(uint4*)(dst + row * APITCH + c4 * 16) = uu;
            }
            if (nw == 0 && lane == 0) tk[p] = grab_slot();
        }

        PAIR_BAR(1 + p);

        if (nw == 0) {
            int cnt = g_cnt[b];
            int j = u * 32 + lane;
            if (j < cnt) {
                float4 a = pedp[lane];
                float4 bb = pedp[32 + lane];
                int s = g_idx[b * NS + j];
                float4 o;
                o.x = a.x + bb.x; o.y = a.y + bb.y;
                o.z = a.z + bb.z; o.w = a.w + bb.w;
                ((float4*)logits)[b * NS + s] = o;
            }
        }

        slot = nslot;
        nslot = (slot >= 0) ? tk[p] : -1;
        buf ^= 1;
    }
}

// ---------------------------------------------------------------------------
// K2: in-place softmax over S for each (b, h). One block per b, 1024 threads.
// ---------------------------------------------------------------------------
__global__ __launch_bounds__(1024) void k2_kernel(float* __restrict__ w)
{
    __shared__ float red[32][4];
    __shared__ float bc[4];
    const int b = blockIdx.x, tid = threadIdx.x;
    const int lane = tid & 31, wid = tid >> 5;

    float4* p = ((float4*)w) + b * NS;
    float4 v[4];
#pragma unroll
    for (int i = 0; i < 4; i++) v[i] = p[tid + 1024 * i];

    float m0 = -3.4e38f, m1 = m0, m2 = m0, m3 = m0;
#pragma unroll
    for (int i = 0; i < 4; i++) {
        m0 = fmaxf(m0, v[i].x); m1 = fmaxf(m1, v[i].y);
        m2 = fmaxf(m2, v[i].z); m3 = fmaxf(m3, v[i].w);
    }
#pragma unroll
    for (int off = 16; off >= 1; off >>= 1) {
        m0 = fmaxf(m0, __shfl_xor_sync(0xffffffffu, m0, off));
        m1 = fmaxf(m1, __shfl_xor_sync(0xffffffffu, m1, off));
        m2 = fmaxf(m2, __shfl_xor_sync(0xffffffffu, m2, off));
        m3 = fmaxf(m3, __shfl_xor_sync(0xffffffffu, m3, off));
    }
    if (lane == 0) { red[wid][0] = m0; red[wid][1] = m1; red[wid][2] = m2; red[wid][3] = m3; }
    __syncthreads();
    if (tid < 4) {
        float m = red[0][tid];
#pragma unroll
        for (int i = 1; i < 32; i++) m = fmaxf(m, red[i][tid]);
        bc[tid] = m;
    }
    __syncthreads();
    m0 = bc[0]; m1 = bc[1]; m2 = bc[2]; m3 = bc[3];

    float s0 = 0.f, s1 = 0.f, s2 = 0.f, s3 = 0.f;
#pragma unroll
    for (int i = 0; i < 4; i++) {
        v[i].x = __expf(v[i].x - m0); s0 += v[i].x;
        v[i].y = __expf(v[i].y - m1); s1 += v[i].y;
        v[i].z = __expf(v[i].z - m2); s2 += v[i].z;
        v[i].w = __expf(v[i].w - m3); s3 += v[i].w;
    }
#pragma unroll
    for (int off = 16; off >= 1; off >>= 1) {
        s0 += __shfl_xor_sync(0xffffffffu, s0, off);
        s1 += __shfl_xor_sync(0xffffffffu, s1, off);
        s2 += __shfl_xor_sync(0xffffffffu, s2, off);
        s3 += __shfl_xor_sync(0xffffffffu, s3, off);
    }
    if (lane == 0) { red[wid][0] = s0; red[wid][1] = s1; red[wid][2] = s2; red[wid][3] = s3; }
    __syncthreads();
    if (tid < 4) {
        float s = 0.f;
#pragma unroll
        for (int i = 0; i < 32; i++) s += red[i][tid];
        bc[tid] = 1.0f / s;
    }
    __syncthreads();
    s0 = bc[0]; s1 = bc[1]; s2 = bc[2]; s3 = bc[3];
#pragma unroll
    for (int i = 0; i < 4; i++) {
        v[i].x *= s0; v[i].y *= s1; v[i].z *= s2; v[i].w *= s3;
        p[tid + 1024 * i] = v[i];
    }
}

// ---------------------------------------------------------------------------
// K3: gather-pooling over compacted rows. Grid (8, 32), 512 threads.
// (EXACT r5 source — proven 12.6 us; do not perturb.)
// ---------------------------------------------------------------------------
__global__ __launch_bounds__(512) void k3_kernel(
    const float* __restrict__ x, const float* __restrict__ w,
    float* __restrict__ part)
{
    __shared__ float sm[16][512];
    const int q = blockIdx.x;    // 0..7
    const int b = blockIdx.y;
    const int tid = threadIdx.x;
    const int d4 = tid & 31;
    const int sg = tid >> 5;

    const int cnt = g_cnt[b];
    const int* ib = g_idx + b * NS;
    const float4* wp = ((const float4*)w) + b * NS;
    const float4* xp = ((const float4*)x) + (size_t)b * NS * 32;

    float a[4][4];
#pragma unroll
    for (int h = 0; h < 4; h++)
#pragma unroll
        for (int j = 0; j < 4; j++) a[h][j] = 0.0f;

    for (int j = q * 16 + sg; j < cnt; j += 128) {
        int s = ib[j];
        float4 wv = wp[s];
        float4 xv = xp[(size_t)s * 32 + d4];
        a[0][0] = fmaf(wv.x, xv.x, a[0][0]); a[0][1] = fmaf(wv.x, xv.y, a[0][1]);
        a[0][2] = fmaf(wv.x, xv.z, a[0][2]); a[0][3] = fmaf(wv.x, xv.w, a[0][3]);
        a[1][0] = fmaf(wv.y, xv.x, a[1][0]); a[1][1] = fmaf(wv.y, xv.y, a[1][1]);
        a[1][2] = fmaf(wv.y, xv.z, a[1][2]); a[1][3] = fmaf(wv.y, xv.w, a[1][3]);
        a[2][0] = fmaf(wv.z, xv.x, a[2][0]); a[2][1] = fmaf(wv.z, xv.y, a[2][1]);
        a[2][2] = fmaf(wv.z, xv.z, a[2][2]); a[2][3] = fmaf(wv.z, xv.w, a[2][3]);
        a[3][0] = fmaf(wv.w, xv.x, a[3][0]); a[3][1] = fmaf(wv.w, xv.y, a[3][1]);
        a[3][2] = fmaf(wv.w, xv.z, a[3][2]); a[3][3] = fmaf(wv.w, xv.w, a[3][3]);
    }
#pragma unroll
    for (int h = 0; h < 4; h++)
#pragma unroll
        for (int j = 0; j < 4; j++)
            sm[sg][h * 128 + d4 * 4 + j] = a[h][j];
    __syncthreads();

    float ssum = 0.0f;
#pragma unroll
    for (int gi = 0; gi < 16; gi++) ssum += sm[gi][tid];
    part[(q * NB + b) * 512 + tid] = ssum;
}

// K4: combine 8 partials -> pooled [B][H][D], float4-wide
__global__ __launch_bounds__(256) void k4_kernel(
    const float4* __restrict__ part, float4* __restrict__ pooled)
{
    int i = blockIdx.x * 256 + threadIdx.x;   // 0..4095 (float4 units)
    float4 s = part[i];
#pragma unroll
    for (int k = 1; k < 8; k++) {
        float4 v = part[k * 4096 + i];
        s.x += v.x; s.y += v.y; s.z += v.z; s.w += v.w;
    }
    pooled[i] = s;
}

// ---------------------------------------------------------------------------
extern "C" void kernel_launch(void* const* d_in, const int* in_sizes, int n_in,
                              void* d_out, int out_size)
{
    const float* x   = (const float*)d_in[0];
    const int*   msk = (const int*)d_in[1];
    const float* Wk  = (const float*)d_in[2];
    const float* Wo  = (const float*)d_in[3];
    float* out = (float*)d_out;

    const int pooled_elems = NB * NH * ND;   // 16384
    const int w_elems = NB * NS * NH;        // 524288

    float* pooled = out;
    float* wbuf;
    if (out_size >= pooled_elems + w_elems) {
        wbuf = out + pooled_elems;
    } else {
        void* p = nullptr;
        cudaGetSymbolAddress(&p, g_w_scratch);
        wbuf = (float*)p;
    }

    cudaFuncSetAttribute(k1_mma_kernel,
                         cudaFuncAttributeMaxDynamicSharedMemorySize, SMEM_K1);

    k0_compact<<<NB, 256>>>(msk, Wk, wbuf);
    k1_mma_kernel<<<GRID1, 256, SMEM_K1>>>(x, Wo, wbuf);
    k2_kernel<<<NB, 1024>>>(wbuf);

    void* pp = nullptr;
    cudaGetSymbolAddress(&pp, g_part);
    k3_kernel<<<dim3(8, NB), 512>>>(x, wbuf, (float*)pp);
    k4_kernel<<<16, 256>>>((const float4*)pp, (float4*)pooled);
}